// round 11
// baseline (speedup 1.0000x reference)
#include <cuda_runtime.h>

// NCN recurrence, decomposed by (batch, head). 2 channels/thread, full-k.
// R10 post-mortem: regs=232 + alu=48.6% with zero source ALU work -- ptxas
// hoisted the unrolled 4-step group's LDS (64 regs/step of x quads) and paid
// ~60 marshaling MOVs/step to keep fma.rn.f32x2 operands pair-aligned.
// Fix: the step-within-group loop is unroll-1 (real backedge = no cross-step
// LDS hoisting; live state = 1 step's quads + weights ~ 160 regs), and
// step indexing uses incrementing pointers instead of q*stride IMADs.
//  * 8 warps x 256 threads: warp = cache slot; thread owns channels
//    (2*lane, 2*lane+1): x staged/read once per slot-step -> minimal LDS.
//  * weights: 64 x u64 f32x2 k-pairs = 128 regs, no spill at 256 thr.
//  * 8-deep per-warp ring, ONE __syncwarp per 4 steps.
//  * tanh(u/2) = 1 - 2/(e^u+1) via ex2.approx + rcp.approx.
//  * ping-pong: one 128MB __device__ static + the x-section of d_out.

#define NB 8
#define NT 4096
#define ND 1024
#define NH 16
#define DH 64
#define NC 8
#define NSTEPS (NT / NC)   // 512
#define NMOD 4
#define BTD (NB * NT * ND) // 33554432

__device__ float g_buf[BTD];

typedef unsigned long long u64;

__device__ __forceinline__ u64 ffma2(u64 a, u64 b, u64 c) {
    u64 d;
    asm("fma.rn.f32x2 %0, %1, %2, %3;" : "=l"(d) : "l"(a), "l"(b), "l"(c));
    return d;
}
__device__ __forceinline__ u64 fadd2(u64 a, u64 b) {
    u64 d;
    asm("add.rn.f32x2 %0, %1, %2;" : "=l"(d) : "l"(a), "l"(b));
    return d;
}
__device__ __forceinline__ u64 packf2(float lo, float hi) {
    u64 d;
    asm("mov.b64 %0, {%1, %2};" : "=l"(d) : "f"(lo), "f"(hi));
    return d;
}
__device__ __forceinline__ float2 unpackf2(u64 v) {
    float lo, hi;
    asm("mov.b64 {%0, %1}, %2;" : "=f"(lo), "=f"(hi) : "l"(v));
    return make_float2(lo, hi);
}

// tanh(0.5f*u) = 1 - 2/(e^u + 1); ~1e-6 abs error.
__device__ __forceinline__ float tanh_half(float u) {
    float e;
    asm("ex2.approx.f32 %0, %1;" : "=f"(e) : "f"(u * 1.4426950408889634f));
    float r;
    asm("rcp.approx.f32 %0, %1;" : "=f"(r) : "f"(e + 1.0f));
    return fmaf(-2.0f, r, 1.0f);
}

__global__ void __launch_bounds__(256, 1)
ncn_kernel(const float* __restrict__ x_in,
           const float* __restrict__ xa_in,
           const float* __restrict__ w_in,
           float* __restrict__ out_x,
           float* __restrict__ out_xa)
{
    __shared__ float shW[DH * DH];     // 16 KB weight staging
    __shared__ float shx[8][8][DH];    // 16 KB: per-warp 8-deep x ring

    const int b    = blockIdx.x >> 4;  // grid = 128 = B * H
    const int h    = blockIdx.x & 15;
    const int warp = threadIdx.x >> 5; // warp == cache slot s (8 warps)
    const int lane = threadIdx.x & 31;
    const int s    = warp;
    const int e0   = 2 * lane;         // this thread's channels e0, e0+1

    // Cache for channels e0,e0+1 of slot s; persists across modules.
    float2 c2 = *(const float2*)(xa_in + (size_t)(b * NC + s) * ND + h * DH + e0);

    // Per-thread weights (2 channels x 32 k-pairs): 64 u64 = 128 regs.
    u64 wA[32], wB[32];

    #pragma unroll 1
    for (int m = 0; m < NMOD; ++m) {
        // Ping-pong: x_in -> g_buf -> out_x -> g_buf -> out_x
        const float* src = (m == 0) ? x_in  : (m & 1) ? g_buf : out_x;
        float*       dst = (m & 1) ? out_x : g_buf;

        __syncthreads();
        const float* wg = w_in + (size_t)(m * NH + h) * DH * DH;
        for (int i = threadIdx.x; i < DH * DH; i += 256) shW[i] = wg[i];
        __syncthreads();
        #pragma unroll
        for (int kp = 0; kp < 32; ++kp) {
            wA[kp] = packf2(shW[(2 * kp) * DH + e0],     shW[(2 * kp + 1) * DH + e0]);
            wB[kp] = packf2(shW[(2 * kp) * DH + e0 + 1], shW[(2 * kp + 1) * DH + e0 + 1]);
        }

        const size_t base   = (size_t)b * NT * ND + (size_t)s * ND + h * DH;
        const size_t stride = (size_t)NC * ND;     // next step of this slot chain
        const float* xp  = src + base + e0;        // staging == compute channels
        float*       ypc = dst + base + e0;        // output cursor (float2 store)

        // ---- prime: stage x(0..3) into bufs 0..3, prefetch x(4..7) ----
        {
            float2 r0 = *(const float2*)(xp);
            float2 r1 = *(const float2*)(xp + stride);
            float2 r2 = *(const float2*)(xp + 2 * stride);
            float2 r3 = *(const float2*)(xp + 3 * stride);
            *(float2*)&shx[warp][0][e0] = r0;
            *(float2*)&shx[warp][1][e0] = r1;
            *(float2*)&shx[warp][2][e0] = r2;
            *(float2*)&shx[warp][3][e0] = r3;
        }
        float2 px0 = *(const float2*)(xp + 4 * stride);
        float2 px1 = *(const float2*)(xp + 5 * stride);
        float2 px2 = *(const float2*)(xp + 6 * stride);
        float2 px3 = *(const float2*)(xp + 7 * stride);
        const float* xpf = xp + 8 * stride;   // LDG cursor: x(p+8) at group p

        // ---- main loop: groups of 4 steps ----
        #pragma unroll 1
        for (int p = 0; p < NSTEPS; p += 4) {
            const int g = (p >> 2) & 1;
            const float* rb = &shx[warp][4 * g][0];        // bufs for x p..p+3
            float*       wb = &shx[warp][4 * (1 - g)][0];  // bufs to refill

            __syncwarp();   // prior group's reads of wb done; prior STS visible

            // unroll 1: real backedge stops ptxas hoisting all 4 steps' LDS
            // (that hoist is what produced regs=232 + ~60 marshaling MOVs/step)
            #pragma unroll 1
            for (int q = 0; q < 4; ++q) {
                const ulonglong2* xs = (const ulonglong2*)(rb + q * DH);
                u64 a0 = 0, a1 = 0, a2 = 0, a3 = 0;
                #pragma unroll
                for (int i = 0; i < 16; ++i) {
                    ulonglong2 xv = xs[i];   // broadcast: x[4i..4i+3]
                    a0 = ffma2(xv.x, wA[2 * i],     a0);
                    a1 = ffma2(xv.y, wA[2 * i + 1], a1);
                    a2 = ffma2(xv.x, wB[2 * i],     a2);
                    a3 = ffma2(xv.y, wB[2 * i + 1], a3);
                }
                float2 f0 = unpackf2(fadd2(a0, a1));  // channel e0
                float2 f1 = unpackf2(fadd2(a2, a3));  // channel e0+1
                // serial part: only this depends on the previous step's c
                c2.x = tanh_half(c2.x + f0.x + f0.y);
                c2.y = tanh_half(c2.y + f1.x + f1.y);
                *(float2*)ypc = c2;
                ypc += stride;
            }

            // stage x(p+4..p+7) into the other 4 buffers
            *(float2*)(wb + 0 * DH + e0) = px0;
            *(float2*)(wb + 1 * DH + e0) = px1;
            *(float2*)(wb + 2 * DH + e0) = px2;
            *(float2*)(wb + 3 * DH + e0) = px3;

            // refill prefetch regs with x(p+8..p+11)
            if (p + 8 < NSTEPS) {
                px0 = *(const float2*)(xpf);
                px1 = *(const float2*)(xpf + stride);
                px2 = *(const float2*)(xpf + 2 * stride);
                px3 = *(const float2*)(xpf + 3 * stride);
            }
            xpf += 4 * stride;
        }
    }

    // Final cache for slot s == its last y value (still in c2).
    *(float2*)(out_xa + (size_t)(b * NC + s) * ND + h * DH + e0) = c2;
}

extern "C" void kernel_launch(void* const* d_in, const int* in_sizes, int n_in,
                              void* d_out, int out_size) {
    const float* x  = (const float*)d_in[0];   // [8, 4096, 1024] fp32
    const float* xa = (const float*)d_in[1];   // [8, 8, 1024]    fp32
    const float* w  = (const float*)d_in[2];   // [4, 16, 64, 64] fp32

    float* out_x  = (float*)d_out;                              // x part
    float* out_xa = (float*)d_out + (out_size - NB * NC * ND);  // xa part (last 65536)

    ncn_kernel<<<NB * NH, 256>>>(x, xa, w, out_x, out_xa);
}